// round 1
// baseline (speedup 1.0000x reference)
#include <cuda_runtime.h>
#include <cstdint>

#define LEAK 0.5f

// Intermediate activation scratch (allocation-free: __device__ globals)
__device__ float g_buf1[32 * 128 * 111 * 111]; // after stage 1 (202 MB)
__device__ float g_buf2[32 * 64 * 54 * 54];    // after stage 2 (24 MB)
__device__ float g_buf3[32 * 32 * 26 * 26];    // after stage 3 (2.8 MB)

__device__ __forceinline__ float* buf_ptr(int which) {
    return which == 1 ? g_buf1 : (which == 2 ? g_buf2 : g_buf3);
}

// ---------------------------------------------------------------------------
// Stage 1: conv(1->128, 3x3) + bias + leaky + maxpool2  : x[32,1,224,224] -> g_buf1[32,128,111,111]
// Block: 256 threads = 16x16 pooled tile. Input tile staged once, reused for all 128 co.
// ---------------------------------------------------------------------------
__global__ __launch_bounds__(256)
void k_conv1(const float* __restrict__ x, const float* __restrict__ w1,
             const float* __restrict__ b1)
{
    __shared__ __align__(16) float sx[34][36];
    __shared__ float sw[128][10];
    __shared__ float sb[128];

    const int n   = blockIdx.z;
    const int ph0 = blockIdx.y * 16, pw0 = blockIdx.x * 16;
    const int ih0 = 2 * ph0, iw0 = 2 * pw0;
    const int t   = threadIdx.x;

    const float* xn = x + (size_t)n * 224 * 224;
    for (int i = t; i < 34 * 34; i += 256) {
        int r = i / 34, c = i % 34;
        int ir = ih0 + r, ic = iw0 + c;
        sx[r][c] = (ir < 224 && ic < 224) ? xn[ir * 224 + ic] : 0.f;
    }
    for (int i = t; i < 128 * 9; i += 256)
        sw[i / 9][i % 9] = (w1[i] >= 0.f) ? 1.f : -1.f;
    if (t < 128) sb[t] = b1[t];
    __syncthreads();

    const int py = t >> 4, px = t & 15;
    const int ph = ph0 + py, pw = pw0 + px;
    const bool valid = (ph < 111) && (pw < 111);

    float xw[4][4];
#pragma unroll
    for (int r = 0; r < 4; r++)
#pragma unroll
        for (int c = 0; c < 4; c++)
            xw[r][c] = sx[2 * py + r][2 * px + c];

    float* op = g_buf1 + ((size_t)n * 128) * (111 * 111) + ph * 111 + pw;

#pragma unroll 2
    for (int co = 0; co < 128; co++) {
        float w[9];
#pragma unroll
        for (int k = 0; k < 9; k++) w[k] = sw[co][k];
        float m = -3.4e38f;
#pragma unroll
        for (int dy = 0; dy < 2; dy++)
#pragma unroll
            for (int dx = 0; dx < 2; dx++) {
                float a = 0.f;
#pragma unroll
                for (int kh = 0; kh < 3; kh++)
#pragma unroll
                    for (int kw = 0; kw < 3; kw++)
                        a += w[kh * 3 + kw] * xw[dy + kh][dx + kw];
                m = fmaxf(m, a);
            }
        m += sb[co];
        m = (m >= 0.f) ? m : LEAK * m;
        if (valid) op[(size_t)co * (111 * 111)] = m;
    }
}

// ---------------------------------------------------------------------------
// Stages 2/3: conv(CI->CO, 3x3) + bias + leaky + maxpool2, smem-tiled direct conv.
// Block: 256 thr = 64 pooled pixels (8x8) x 4 co-groups; each thread: 2x2 conv
// positions x 4 output channels = 16 fp32 accumulators.
// Input staged per 16-channel chunk; weights binarized into smem as [ci][tap][co]
// so per-thread 4 co's load as one broadcast LDS.128.
// ---------------------------------------------------------------------------
template<int CI, int CO, int HIN, int POUT, int IBUF, int OBUF>
__global__ __launch_bounds__(256)
void k_conv_pool(const float* __restrict__ wg, const float* __restrict__ bg)
{
    constexpr int CI_CHUNK = 16;
    constexpr int CO_TILE  = 16;
    constexpr int NTX      = (POUT + 7) / 8;

    __shared__ __align__(16) float sx[CI_CHUNK][18][20];
    __shared__ __align__(16) float sw[CI_CHUNK][9][CO_TILE];

    const float* in  = buf_ptr(IBUF);
    float*       out = buf_ptr(OBUF);

    const int n   = blockIdx.z;
    const int co0 = blockIdx.y * CO_TILE;
    const int ty  = blockIdx.x / NTX, tx = blockIdx.x % NTX;
    const int ph0 = ty * 8, pw0 = tx * 8;
    const int ih0 = 2 * ph0, iw0 = 2 * pw0;

    const int t   = threadIdx.x;
    const int pix = t & 63, cg = t >> 6;
    const int py  = pix >> 3, px = pix & 7;

    const float* xn = in + ((size_t)n * CI) * (HIN * HIN);

    float acc[2][2][4];
#pragma unroll
    for (int dy = 0; dy < 2; dy++)
#pragma unroll
        for (int dx = 0; dx < 2; dx++)
#pragma unroll
            for (int j = 0; j < 4; j++) acc[dy][dx][j] = 0.f;

    for (int cc = 0; cc < CI; cc += CI_CHUNK) {
        // stage input tile [16ch][18][18] (padded rows)
        for (int i = t; i < CI_CHUNK * 18 * 18; i += 256) {
            int ci  = i / (18 * 18);
            int rem = i % (18 * 18);
            int r = rem / 18, c = rem % 18;
            int ir = ih0 + r, ic = iw0 + c;
            float v = (ir < HIN && ic < HIN)
                          ? xn[(size_t)(cc + ci) * (HIN * HIN) + ir * HIN + ic]
                          : 0.f;
            sx[ci][r][c] = v;
        }
        // stage binarized weights [ci][tap][co]
        for (int i = t; i < CI_CHUNK * 9 * CO_TILE; i += 256) {
            int co  = i % CO_TILE;
            int rem = i / CO_TILE;
            int k   = rem % 9;
            int ci  = rem / 9;
            float v = wg[(((size_t)(co0 + co)) * CI + (cc + ci)) * 9 + k];
            sw[ci][k][co] = (v >= 0.f) ? 1.f : -1.f;
        }
        __syncthreads();

#pragma unroll 2
        for (int ci = 0; ci < CI_CHUNK; ci++) {
            float xw[4][4];
#pragma unroll
            for (int r = 0; r < 4; r++) {
                float2 a  = *(const float2*)&sx[ci][2 * py + r][2 * px];
                float2 b2 = *(const float2*)&sx[ci][2 * py + r][2 * px + 2];
                xw[r][0] = a.x;  xw[r][1] = a.y;
                xw[r][2] = b2.x; xw[r][3] = b2.y;
            }
#pragma unroll
            for (int kh = 0; kh < 3; kh++)
#pragma unroll
                for (int kw = 0; kw < 3; kw++) {
                    float4 wv = *(const float4*)&sw[ci][kh * 3 + kw][cg * 4];
#pragma unroll
                    for (int dy = 0; dy < 2; dy++)
#pragma unroll
                        for (int dx = 0; dx < 2; dx++) {
                            float xv = xw[dy + kh][dx + kw];
                            acc[dy][dx][0] += wv.x * xv;
                            acc[dy][dx][1] += wv.y * xv;
                            acc[dy][dx][2] += wv.z * xv;
                            acc[dy][dx][3] += wv.w * xv;
                        }
                }
        }
        __syncthreads();
    }

    const int ph = ph0 + py, pw = pw0 + px;
    if (ph < POUT && pw < POUT) {
#pragma unroll
        for (int j = 0; j < 4; j++) {
            int co = co0 + cg * 4 + j;
            float m = fmaxf(fmaxf(acc[0][0][j], acc[0][1][j]),
                            fmaxf(acc[1][0][j], acc[1][1][j]));
            m += __ldg(&bg[co]);
            m = (m >= 0.f) ? m : LEAK * m;
            out[(((size_t)n * CO + co) * POUT + ph) * POUT + pw] = m;
        }
    }
}

// ---------------------------------------------------------------------------
// Stage 4: conv(32->8, kh=3 kw=2) + bias, no pool.  g_buf3[32,32,26,26] -> d_out[32,4800]
// ---------------------------------------------------------------------------
__global__ __launch_bounds__(256)
void k_conv4(const float* __restrict__ w4, const float* __restrict__ b4,
             float* __restrict__ out)
{
    __shared__ float sw[8][32][3][2];
    __shared__ float sb[8];
    const int t = threadIdx.x;
    for (int i = t; i < 8 * 32 * 6; i += 256)
        ((float*)sw)[i] = (w4[i] >= 0.f) ? 1.f : -1.f;
    if (t < 8) sb[t] = b4[t];
    __syncthreads();

    int idx = blockIdx.x * 256 + t;
    if (idx >= 32 * 8 * 24 * 25) return;
    int ow = idx % 25; int r = idx / 25;
    int oh = r % 24;   r /= 24;
    int co = r % 8;    int n = r / 8;

    const float* xn = g_buf3 + ((size_t)n * 32) * (26 * 26);
    float a = sb[co];
#pragma unroll 4
    for (int ci = 0; ci < 32; ci++) {
        const float* xr = xn + ci * 676 + oh * 26 + ow;
#pragma unroll
        for (int kh = 0; kh < 3; kh++)
#pragma unroll
            for (int kw = 0; kw < 2; kw++)
                a += sw[co][ci][kh][kw] * __ldg(&xr[kh * 26 + kw]);
    }
    out[idx] = a;
}

// ---------------------------------------------------------------------------
extern "C" void kernel_launch(void* const* d_in, const int* in_sizes, int n_in,
                              void* d_out, int out_size)
{
    (void)in_sizes; (void)n_in; (void)out_size;
    const float* x  = (const float*)d_in[0];
    const float* w1 = (const float*)d_in[1];
    const float* b1 = (const float*)d_in[2];
    const float* w2 = (const float*)d_in[3];
    const float* b2 = (const float*)d_in[4];
    const float* w3 = (const float*)d_in[5];
    const float* b3 = (const float*)d_in[6];
    const float* w4 = (const float*)d_in[7];
    const float* b4 = (const float*)d_in[8];
    float* out = (float*)d_out;

    // Stage 1: pooled 111x111 -> 7x7 tiles of 16x16
    k_conv1<<<dim3(7, 7, 32), 256>>>(x, w1, b1);

    // Stage 2: CI=128 CO=64 HIN=111 POUT=54 ; spatial 7x7 tiles, 4 co-groups
    k_conv_pool<128, 64, 111, 54, 1, 2><<<dim3(49, 4, 32), 256>>>(w2, b2);

    // Stage 3: CI=64 CO=32 HIN=54 POUT=26 ; spatial 4x4 tiles, 2 co-groups
    k_conv_pool<64, 32, 54, 26, 2, 3><<<dim3(16, 2, 32), 256>>>(w3, b3);

    // Stage 4: 32*8*24*25 = 153600 outputs
    k_conv4<<<dim3((32 * 8 * 24 * 25 + 255) / 256), 256>>>(w4, b4, out);
}